// round 16
// baseline (speedup 1.0000x reference)
#include <cuda_runtime.h>
#include <math.h>

#define GRIDB 256   // tail grid: every block does gram AND listmle
#define NSLOT 16    // gram partial slots (k=64 granularity)

// ---------------- scratch (device globals; no allocations) ----------------
__device__ float g_means[2][2][256][1024];  // [half][tensor][class][d] partial sums
__device__ float g_gram[NSLOT][2][256][256];// partial grams (odd diag slots stay 0)
__device__ float g_rowloss[256];
__device__ int   g_bar1, g_done;            // counters (self-resetting)

__constant__ unsigned char c_pi[6] = {0,0,0,1,1,2};
__constant__ unsigned char c_pj[6] = {1,2,3,2,3,3};

// ================= kernel A: means (3-stage, best measured 24.7us) ==========
// grid 1024 = half(2) x tensor(2) x class(256); block 128 = 4 warps.
#define STAGES 3
__global__ void __launch_bounds__(128) means_kernel(const float* __restrict__ emb,
                                                    const float* __restrict__ feat) {
    __shared__ float4 s_buf[STAGES][4][256];   // 48 KB exactly

    int b = blockIdx.x;
    int c = b & 255;
    int t = (b >> 8) & 1;
    int h = b >> 9;                            // sample half: [h*32, h*32+32)
    const float4* xv = (const float4*)((t == 0 ? emb : feat) + (size_t)c * 64 * 1024);
    int tid = threadIdx.x, lane = tid & 31, w = tid >> 5;

    const float4* base4 = xv + (size_t)(h * 32 + w * 8) * 256;

    float4 acc[8];
    #pragma unroll
    for (int j = 0; j < 8; j++) acc[j] = make_float4(0.f, 0.f, 0.f, 0.f);

    #define ISSUE(n, st) do {                                                       \
        unsigned _d = (unsigned)__cvta_generic_to_shared(&s_buf[(st)][w][lane]);    \
        const float4* _s = base4 + (size_t)(n) * 256 + lane;                        \
        _Pragma("unroll")                                                           \
        for (int j = 0; j < 8; j++)                                                 \
            asm volatile("cp.async.cg.shared.global [%0], [%1], 16;"                \
                         :: "r"(_d + j * 512), "l"(_s + j * 32));                   \
        asm volatile("cp.async.commit_group;");                                     \
    } while (0)

    ISSUE(0, 0); ISSUE(1, 1); ISSUE(2, 2);

    #pragma unroll 1
    for (int n = 0; n < 8; n++) {
        asm volatile("cp.async.wait_group 2;" ::: "memory");
        int st = n % 3;

        float4 v[8];
        #pragma unroll
        for (int j = 0; j < 8; j++) v[j] = s_buf[st][w][j * 32 + lane];

        if (n + STAGES < 8) { ISSUE(n + STAGES, st); }
        else { asm volatile("cp.async.commit_group;"); }

        float ss = 0.f;
        #pragma unroll
        for (int j = 0; j < 8; j++)
            ss += v[j].x * v[j].x + v[j].y * v[j].y + v[j].z * v[j].z + v[j].w * v[j].w;
        #pragma unroll
        for (int o = 16; o; o >>= 1) ss += __shfl_xor_sync(0xffffffffu, ss, o);

        float inv = 1.0f / fmaxf(sqrtf(ss), 1e-12f);
        #pragma unroll
        for (int j = 0; j < 8; j++) {
            acc[j].x += v[j].x * inv;
            acc[j].y += v[j].y * inv;
            acc[j].z += v[j].z * inv;
            acc[j].w += v[j].w * inv;
        }
    }
    #undef ISSUE

    #pragma unroll
    for (int j = 0; j < 8; j++) s_buf[0][w][j * 32 + lane] = acc[j];
    __syncthreads();

    #pragma unroll
    for (int i = tid; i < 256; i += 128) {
        float4 r = s_buf[0][0][i];
        #pragma unroll
        for (int w2 = 1; w2 < 4; w2++) {
            float4 u = s_buf[0][w2][i];
            r.x += u.x; r.y += u.y; r.z += u.z; r.w += u.w;
        }
        ((float4*)&g_means[h][t][c][0])[i] = r;  // SUM; /64 folded into gram scale
    }
}

// ================= kernel B: gram(256 blocks) -> barrier -> listmle =========
// Items (halved FLOPs via symmetry), exactly 256:
//   bid 0..191 : off-diag pair(6) x tensor(2) x ks(16, k=64) -> slot ks
//   bid 192..255: diag tile(4) x tensor(2) x ks(8, k=128 as 2x64) -> slot 2*ks
__device__ __forceinline__ void grid_barrier_b() {
    __syncthreads();
    if (threadIdx.x == 0) {
        __threadfence();
        atomicAdd(&g_bar1, 1);
        while (*((volatile int*)&g_bar1) < GRIDB) __nanosleep(64);
    }
    __syncthreads();
}

__global__ void __launch_bounds__(128, 4) tail_kernel(float* __restrict__ out) {
    __shared__ float As[64][68];   // i-tile (k x row), also transpose buffer
    __shared__ float Bs[64][68];   // j-tile
    __shared__ float s_red[4];
    __shared__ int   s_last;

    int tid = threadIdx.x, lane = tid & 31, w = tid >> 5;
    int tx = tid & 15, ty = tid >> 4;
    const float scale = 1.0f / 4096.0f;   // (1/64)^2 from the two means

    float acc[8][4];
    #pragma unroll
    for (int u = 0; u < 8; u++)
        #pragma unroll
        for (int v = 0; v < 4; v++) acc[u][v] = 0.f;

    // ---------------- gram phase ----------------
    if (blockIdx.x < 192) {
        // off-diagonal tile, k-chunk of 64 -> slot ks
        int bid  = blockIdx.x;
        int ks   = bid & 15;
        int rest = bid >> 4;        // 0..11
        int t    = rest & 1;
        int pr   = rest >> 1;       // 0..5
        int i0 = c_pi[pr] * 64, j0 = c_pj[pr] * 64;
        const float* A0 = &g_means[0][t][0][0];
        const float* A1 = &g_means[1][t][0][0];
        int kk = ks * 64;

        #pragma unroll
        for (int l = 0; l < 8; l++) {
            int idx = tid + l * 128;
            int r = idx >> 4, f4 = idx & 15;
            size_t oi = (size_t)(i0 + r) * 1024 + kk + f4 * 4;
            size_t oj = (size_t)(j0 + r) * 1024 + kk + f4 * 4;
            float4 a0 = *(const float4*)&A0[oi];
            float4 a1 = *(const float4*)&A1[oi];
            As[f4 * 4 + 0][r] = a0.x + a1.x;
            As[f4 * 4 + 1][r] = a0.y + a1.y;
            As[f4 * 4 + 2][r] = a0.z + a1.z;
            As[f4 * 4 + 3][r] = a0.w + a1.w;
            float4 b0 = *(const float4*)&A0[oj];
            float4 b1 = *(const float4*)&A1[oj];
            Bs[f4 * 4 + 0][r] = b0.x + b1.x;
            Bs[f4 * 4 + 1][r] = b0.y + b1.y;
            Bs[f4 * 4 + 2][r] = b0.z + b1.z;
            Bs[f4 * 4 + 3][r] = b0.w + b1.w;
        }
        __syncthreads();

        #pragma unroll 4
        for (int k = 0; k < 64; k++) {
            float4 a0 = *(const float4*)&As[k][ty * 8];
            float4 a1 = *(const float4*)&As[k][ty * 8 + 4];
            float4 bb = *(const float4*)&Bs[k][tx * 4];
            acc[0][0] += a0.x * bb.x; acc[0][1] += a0.x * bb.y; acc[0][2] += a0.x * bb.z; acc[0][3] += a0.x * bb.w;
            acc[1][0] += a0.y * bb.x; acc[1][1] += a0.y * bb.y; acc[1][2] += a0.y * bb.z; acc[1][3] += a0.y * bb.w;
            acc[2][0] += a0.z * bb.x; acc[2][1] += a0.z * bb.y; acc[2][2] += a0.z * bb.z; acc[2][3] += a0.z * bb.w;
            acc[3][0] += a0.w * bb.x; acc[3][1] += a0.w * bb.y; acc[3][2] += a0.w * bb.z; acc[3][3] += a0.w * bb.w;
            acc[4][0] += a1.x * bb.x; acc[4][1] += a1.x * bb.y; acc[4][2] += a1.x * bb.z; acc[4][3] += a1.x * bb.w;
            acc[5][0] += a1.y * bb.x; acc[5][1] += a1.y * bb.y; acc[5][2] += a1.y * bb.z; acc[5][3] += a1.y * bb.w;
            acc[6][0] += a1.z * bb.x; acc[6][1] += a1.z * bb.y; acc[6][2] += a1.z * bb.z; acc[6][3] += a1.z * bb.w;
            acc[7][0] += a1.w * bb.x; acc[7][1] += a1.w * bb.y; acc[7][2] += a1.w * bb.z; acc[7][3] += a1.w * bb.w;
        }

        __syncthreads();   // done reading tiles; reuse As for transpose
        #pragma unroll
        for (int u = 0; u < 8; u++) {
            float4 o4 = make_float4(acc[u][0] * scale, acc[u][1] * scale,
                                    acc[u][2] * scale, acc[u][3] * scale);
            *(float4*)&g_gram[ks][t][i0 + ty * 8 + u][j0 + tx * 4] = o4;
            As[ty * 8 + u][tx * 4 + 0] = o4.x;
            As[ty * 8 + u][tx * 4 + 1] = o4.y;
            As[ty * 8 + u][tx * 4 + 2] = o4.z;
            As[ty * 8 + u][tx * 4 + 3] = o4.w;
        }
        __syncthreads();
        #pragma unroll
        for (int u = 0; u < 8; u++) {   // coalesced mirror via smem transpose
            int rr = ty * 8 + u;
            float4 m4 = make_float4(As[tx * 4 + 0][rr], As[tx * 4 + 1][rr],
                                    As[tx * 4 + 2][rr], As[tx * 4 + 3][rr]);
            *(float4*)&g_gram[ks][t][j0 + rr][i0 + tx * 4] = m4;
        }
    } else {
        // diagonal tile, k-chunk of 128 done as 2 accumulated k=64 sub-fills
        int d    = blockIdx.x - 192;   // 0..63
        int ks   = d & 7;              // 8 chunks of k=128
        int rest = d >> 3;             // 0..7
        int t    = rest & 1;
        int di   = rest >> 1;          // 0..3
        int i0 = di * 64;
        const float* A0 = &g_means[0][t][0][0];
        const float* A1 = &g_means[1][t][0][0];

        #pragma unroll 1
        for (int sub = 0; sub < 2; sub++) {
            int kk = ks * 128 + sub * 64;
            #pragma unroll
            for (int l = 0; l < 8; l++) {
                int idx = tid + l * 128;
                int r = idx >> 4, f4 = idx & 15;
                size_t oi = (size_t)(i0 + r) * 1024 + kk + f4 * 4;
                float4 a0 = *(const float4*)&A0[oi];
                float4 a1 = *(const float4*)&A1[oi];
                As[f4 * 4 + 0][r] = a0.x + a1.x;
                As[f4 * 4 + 1][r] = a0.y + a1.y;
                As[f4 * 4 + 2][r] = a0.z + a1.z;
                As[f4 * 4 + 3][r] = a0.w + a1.w;
            }
            __syncthreads();

            #pragma unroll 4
            for (int k = 0; k < 64; k++) {
                float4 a0 = *(const float4*)&As[k][ty * 8];
                float4 a1 = *(const float4*)&As[k][ty * 8 + 4];
                float4 bb = *(const float4*)&As[k][tx * 4];
                acc[0][0] += a0.x * bb.x; acc[0][1] += a0.x * bb.y; acc[0][2] += a0.x * bb.z; acc[0][3] += a0.x * bb.w;
                acc[1][0] += a0.y * bb.x; acc[1][1] += a0.y * bb.y; acc[1][2] += a0.y * bb.z; acc[1][3] += a0.y * bb.w;
                acc[2][0] += a0.z * bb.x; acc[2][1] += a0.z * bb.y; acc[2][2] += a0.z * bb.z; acc[2][3] += a0.z * bb.w;
                acc[3][0] += a0.w * bb.x; acc[3][1] += a0.w * bb.y; acc[3][2] += a0.w * bb.z; acc[3][3] += a0.w * bb.w;
                acc[4][0] += a1.x * bb.x; acc[4][1] += a1.x * bb.y; acc[4][2] += a1.x * bb.z; acc[4][3] += a1.x * bb.w;
                acc[5][0] += a1.y * bb.x; acc[5][1] += a1.y * bb.y; acc[5][2] += a1.y * bb.z; acc[5][3] += a1.y * bb.w;
                acc[6][0] += a1.z * bb.x; acc[6][1] += a1.z * bb.y; acc[6][2] += a1.z * bb.z; acc[6][3] += a1.z * bb.w;
                acc[7][0] += a1.w * bb.x; acc[7][1] += a1.w * bb.y; acc[7][2] += a1.w * bb.z; acc[7][3] += a1.w * bb.w;
            }
            __syncthreads();   // before next sub-fill overwrites As
        }

        #pragma unroll
        for (int u = 0; u < 8; u++) {
            float4 o4 = make_float4(acc[u][0] * scale, acc[u][1] * scale,
                                    acc[u][2] * scale, acc[u][3] * scale);
            // slot 2*ks covers k in [128ks, 128ks+128); slot 2*ks+1 stays zero
            *(float4*)&g_gram[2 * ks][t][i0 + ty * 8 + u][i0 + tx * 4] = o4;
        }
    }

    grid_barrier_b();

    // ---------------- listmle phase: ALL 256 blocks, one row each -----------
    {
        int i = blockIdx.x;
        float* tr = &As[0][0];
        float* ps = &Bs[0][0];

        float p0 = 0.f, t0 = 0.f, p1 = 0.f, t1 = 0.f;
        #pragma unroll
        for (int ks = 0; ks < NSLOT; ks++) {
            p0 += g_gram[ks][0][i][tid];
            p1 += g_gram[ks][0][i][tid + 128];
            t0 += g_gram[ks][1][i][tid];
            t1 += g_gram[ks][1][i][tid + 128];
        }
        tr[tid] = t0; tr[tid + 128] = t1;
        __syncthreads();

        // stable descending rank (ties keep ascending index = argsort(-true))
        int r0 = 0, r1 = 0;
        #pragma unroll 8
        for (int k = 0; k < 256; k++) {
            float tk = tr[k];
            r0 += (tk > t0) || (tk == t0 && k < tid);
            r1 += (tk > t1) || (tk == t1 && k < tid + 128);
        }
        ps[r0] = p0;
        ps[r1] = p1;
        __syncthreads();

        // thread owns sorted positions (2*tid, 2*tid+1)
        float e0 = ps[2 * tid], e1 = ps[2 * tid + 1];
        float x0 = __expf(e0), x1 = __expf(e1);
        float s = x0 + x1;

        #pragma unroll
        for (int off = 1; off < 32; off <<= 1) {
            float v = __shfl_down_sync(0xffffffffu, s, off);
            if (lane + off < 32) s += v;
        }
        if (lane == 0) s_red[w] = s;
        __syncthreads();
        float tail = 0.f;
        #pragma unroll
        for (int w2 = 0; w2 < 4; w2++) if (w2 > w) tail += s_red[w2];
        float S = s + tail;                 // suffix sum at position 2*tid

        float term = (__logf(S + 1e-10f) - e0)
                   + (__logf(S - x0 + 1e-10f) - e1);
        __syncthreads();
        #pragma unroll
        for (int o = 16; o; o >>= 1) term += __shfl_xor_sync(0xffffffffu, term, o);
        if (lane == 0) s_red[w] = term;
        __syncthreads();
        if (tid == 0) {
            g_rowloss[i] = s_red[0] + s_red[1] + s_red[2] + s_red[3];
            __threadfence();
            int v = atomicAdd(&g_done, 1);
            s_last = (v == 255);
        }
        __syncthreads();

        if (s_last) {
            volatile float* rl = g_rowloss;
            float v = rl[tid] + rl[tid + 128];
            #pragma unroll
            for (int o = 16; o; o >>= 1) v += __shfl_xor_sync(0xffffffffu, v, o);
            if (lane == 0) s_red[w] = v;
            __syncthreads();
            if (tid == 0) {
                out[0] = (s_red[0] + s_red[1] + s_red[2] + s_red[3]) * (1.0f / 256.0f);
                g_done = 0;   // reset counters for next graph replay
                g_bar1 = 0;
            }
        }
    }
}

// ---------------- launch ----------------
extern "C" void kernel_launch(void* const* d_in, const int* in_sizes, int n_in,
                              void* d_out, int out_size) {
    const float* emb  = (const float*)d_in[0];
    const float* feat = (const float*)d_in[1];
    float* out = (float*)d_out;

    means_kernel<<<1024, 128>>>(emb, feat);
    tail_kernel<<<GRIDB, 128>>>(out);
}

// round 17
// speedup vs baseline: 1.2083x; 1.2083x over previous
#include <cuda_runtime.h>
#include <math.h>

#define CK 4   // k-split for gram: k=256 per block

// ---------------- scratch (device globals; no allocations) ----------------
__device__ float g_means[2][2][256][1024]; // [half][tensor][class][d] partial sums
__device__ float g_gram[CK][2][256][256];  // partial grams
__device__ float g_rowloss[256];
__device__ int   g_done;                   // last-block counter (self-resetting)

// ================= kernel A: means (3-stage, best measured 24.7us) ==========
// grid 1024 = half(2) x tensor(2) x class(256); block 128 = 4 warps.
#define STAGES 3
__global__ void __launch_bounds__(128) means_kernel(const float* __restrict__ emb,
                                                    const float* __restrict__ feat) {
    __shared__ float4 s_buf[STAGES][4][256];   // 48 KB exactly

    int b = blockIdx.x;
    int c = b & 255;
    int t = (b >> 8) & 1;
    int h = b >> 9;                            // sample half: [h*32, h*32+32)
    const float4* xv = (const float4*)((t == 0 ? emb : feat) + (size_t)c * 64 * 1024);
    int tid = threadIdx.x, lane = tid & 31, w = tid >> 5;

    const float4* base4 = xv + (size_t)(h * 32 + w * 8) * 256;

    float4 acc[8];
    #pragma unroll
    for (int j = 0; j < 8; j++) acc[j] = make_float4(0.f, 0.f, 0.f, 0.f);

    #define ISSUE(n, st) do {                                                       \
        unsigned _d = (unsigned)__cvta_generic_to_shared(&s_buf[(st)][w][lane]);    \
        const float4* _s = base4 + (size_t)(n) * 256 + lane;                        \
        _Pragma("unroll")                                                           \
        for (int j = 0; j < 8; j++)                                                 \
            asm volatile("cp.async.cg.shared.global [%0], [%1], 16;"                \
                         :: "r"(_d + j * 512), "l"(_s + j * 32));                   \
        asm volatile("cp.async.commit_group;");                                     \
    } while (0)

    ISSUE(0, 0); ISSUE(1, 1); ISSUE(2, 2);

    #pragma unroll 1
    for (int n = 0; n < 8; n++) {
        asm volatile("cp.async.wait_group 2;" ::: "memory");
        int st = n % 3;

        float4 v[8];
        #pragma unroll
        for (int j = 0; j < 8; j++) v[j] = s_buf[st][w][j * 32 + lane];

        if (n + STAGES < 8) { ISSUE(n + STAGES, st); }
        else { asm volatile("cp.async.commit_group;"); }

        float ss = 0.f;
        #pragma unroll
        for (int j = 0; j < 8; j++)
            ss += v[j].x * v[j].x + v[j].y * v[j].y + v[j].z * v[j].z + v[j].w * v[j].w;
        #pragma unroll
        for (int o = 16; o; o >>= 1) ss += __shfl_xor_sync(0xffffffffu, ss, o);

        float inv = 1.0f / fmaxf(sqrtf(ss), 1e-12f);
        #pragma unroll
        for (int j = 0; j < 8; j++) {
            acc[j].x += v[j].x * inv;
            acc[j].y += v[j].y * inv;
            acc[j].z += v[j].z * inv;
            acc[j].w += v[j].w * inv;
        }
    }
    #undef ISSUE

    #pragma unroll
    for (int j = 0; j < 8; j++) s_buf[0][w][j * 32 + lane] = acc[j];
    __syncthreads();

    #pragma unroll
    for (int i = tid; i < 256; i += 128) {
        float4 r = s_buf[0][0][i];
        #pragma unroll
        for (int w2 = 1; w2 < 4; w2++) {
            float4 u = s_buf[0][w2][i];
            r.x += u.x; r.y += u.y; r.z += u.z; r.w += u.w;
        }
        ((float4*)&g_means[h][t][c][0])[i] = r;  // SUM; /64 folded into gram scale
    }
}

// ================= kernel B: gram (R3 shape: 128 blocks x 256 thr, CK=4) ====
// grid (4 jtile, 4 itile, 2*CK); each block: one 64x64 tile, k in [ks*256,+256)
// via four k=64 smem passes. 4x4 micro-tile, plain scalar FFMA, float4 stores.
__global__ void __launch_bounds__(256) gram_kernel() {
    __shared__ float As[64][68];  // transposed: As[k][row]
    __shared__ float Bs[64][68];

    int t  = blockIdx.z >> 2;     // CK == 4
    int ks = blockIdx.z & 3;
    int i0 = blockIdx.y * 64;
    int j0 = blockIdx.x * 64;
    const float* A0 = &g_means[0][t][0][0];
    const float* A1 = &g_means[1][t][0][0];

    int tid = threadIdx.x;
    int tx = tid & 15, ty = tid >> 4;

    float acc[4][4];
    #pragma unroll
    for (int u = 0; u < 4; u++)
        #pragma unroll
        for (int v = 0; v < 4; v++) acc[u][v] = 0.f;

    int kbase = ks * 256;
    for (int kk = kbase; kk < kbase + 256; kk += 64) {
        #pragma unroll
        for (int l = 0; l < 4; l++) {
            int idx = tid + l * 256;
            int r   = idx >> 4;     // 0..63
            int f4  = idx & 15;     // 0..15
            size_t oi = (size_t)(i0 + r) * 1024 + kk + f4 * 4;
            size_t oj = (size_t)(j0 + r) * 1024 + kk + f4 * 4;
            float4 a0 = *(const float4*)&A0[oi];
            float4 a1 = *(const float4*)&A1[oi];
            As[f4 * 4 + 0][r] = a0.x + a1.x;
            As[f4 * 4 + 1][r] = a0.y + a1.y;
            As[f4 * 4 + 2][r] = a0.z + a1.z;
            As[f4 * 4 + 3][r] = a0.w + a1.w;
            float4 b0 = *(const float4*)&A0[oj];
            float4 b1 = *(const float4*)&A1[oj];
            Bs[f4 * 4 + 0][r] = b0.x + b1.x;
            Bs[f4 * 4 + 1][r] = b0.y + b1.y;
            Bs[f4 * 4 + 2][r] = b0.z + b1.z;
            Bs[f4 * 4 + 3][r] = b0.w + b1.w;
        }
        __syncthreads();
        #pragma unroll
        for (int k = 0; k < 64; k++) {
            float4 a = *(const float4*)&As[k][ty * 4];
            float4 bb = *(const float4*)&Bs[k][tx * 4];
            acc[0][0] += a.x * bb.x; acc[0][1] += a.x * bb.y; acc[0][2] += a.x * bb.z; acc[0][3] += a.x * bb.w;
            acc[1][0] += a.y * bb.x; acc[1][1] += a.y * bb.y; acc[1][2] += a.y * bb.z; acc[1][3] += a.y * bb.w;
            acc[2][0] += a.z * bb.x; acc[2][1] += a.z * bb.y; acc[2][2] += a.z * bb.z; acc[2][3] += a.z * bb.w;
            acc[3][0] += a.w * bb.x; acc[3][1] += a.w * bb.y; acc[3][2] += a.w * bb.z; acc[3][3] += a.w * bb.w;
        }
        __syncthreads();
    }

    const float scale = 1.0f / 4096.0f;   // (1/64)^2 from the two means
    #pragma unroll
    for (int u = 0; u < 4; u++) {
        float4 o4 = make_float4(acc[u][0] * scale, acc[u][1] * scale,
                                acc[u][2] * scale, acc[u][3] * scale);
        *(float4*)&g_gram[ks][t][i0 + ty * 4 + u][j0 + tx * 4] = o4;
    }
}

// ================= kernel C: ListMLE per row + fused final mean =============
// grid 256 x 128 thr; thread handles cols (tid, tid+128); pair suffix scan.
__global__ void __launch_bounds__(128) listmle_kernel(float* __restrict__ out) {
    __shared__ float tr[256];
    __shared__ float ps[256];
    __shared__ float s_red[4];
    __shared__ int   s_last;

    int i = blockIdx.x, tid = threadIdx.x;
    int lane = tid & 31, w = tid >> 5;

    float p0 = 0.f, t0 = 0.f, p1 = 0.f, t1 = 0.f;
    #pragma unroll
    for (int ks = 0; ks < CK; ks++) {
        p0 += g_gram[ks][0][i][tid];
        p1 += g_gram[ks][0][i][tid + 128];
        t0 += g_gram[ks][1][i][tid];
        t1 += g_gram[ks][1][i][tid + 128];
    }
    tr[tid] = t0; tr[tid + 128] = t1;
    __syncthreads();

    // stable descending rank (ties keep ascending index = argsort(-true))
    int r0 = 0, r1 = 0;
    #pragma unroll 8
    for (int k = 0; k < 256; k++) {
        float tk = tr[k];
        r0 += (tk > t0) || (tk == t0 && k < tid);
        r1 += (tk > t1) || (tk == t1 && k < tid + 128);
    }
    ps[r0] = p0;
    ps[r1] = p1;
    __syncthreads();

    // thread owns sorted positions (2*tid, 2*tid+1)
    float e0 = ps[2 * tid], e1 = ps[2 * tid + 1];
    float x0 = __expf(e0), x1 = __expf(e1);
    float s = x0 + x1;

    #pragma unroll
    for (int off = 1; off < 32; off <<= 1) {
        float v = __shfl_down_sync(0xffffffffu, s, off);
        if (lane + off < 32) s += v;
    }
    if (lane == 0) s_red[w] = s;
    __syncthreads();
    float tail = 0.f;
    #pragma unroll
    for (int w2 = 0; w2 < 4; w2++) if (w2 > w) tail += s_red[w2];
    float S = s + tail;                 // suffix sum at position 2*tid

    float term = (__logf(S + 1e-10f) - e0)
               + (__logf(S - x0 + 1e-10f) - e1);
    __syncthreads();
    #pragma unroll
    for (int o = 16; o; o >>= 1) term += __shfl_xor_sync(0xffffffffu, term, o);
    if (lane == 0) s_red[w] = term;
    __syncthreads();
    if (tid == 0) {
        g_rowloss[i] = s_red[0] + s_red[1] + s_red[2] + s_red[3];
        __threadfence();
        int v = atomicAdd(&g_done, 1);
        s_last = (v == 255);
    }
    __syncthreads();

    if (s_last) {
        volatile float* rl = g_rowloss;
        float v = rl[tid] + rl[tid + 128];
        #pragma unroll
        for (int o = 16; o; o >>= 1) v += __shfl_xor_sync(0xffffffffu, v, o);
        if (lane == 0) s_red[w] = v;
        __syncthreads();
        if (tid == 0) {
            out[0] = (s_red[0] + s_red[1] + s_red[2] + s_red[3]) * (1.0f / 256.0f);
            g_done = 0;   // self-reset for next graph replay
        }
    }
}

// ---------------- launch ----------------
extern "C" void kernel_launch(void* const* d_in, const int* in_sizes, int n_in,
                              void* d_out, int out_size) {
    const float* emb  = (const float*)d_in[0];
    const float* feat = (const float*)d_in[1];
    float* out = (float*)d_out;

    means_kernel<<<1024, 128>>>(emb, feat);
    gram_kernel<<<dim3(4, 4, 2 * CK), 256>>>();
    listmle_kernel<<<256, 128>>>(out);
}